// round 3
// baseline (speedup 1.0000x reference)
#include <cuda_runtime.h>
#include <math.h>

#define NN 40000
#define CC 128
#define EE 640000
#define GG 64
#define NKI 15

// ---------------- device scratch (no allocations allowed) ----------------
__device__ float g_xA[NN*CC];
__device__ float g_xB[NN*CC];
__device__ float g_agg[NN*CC];
__device__ float g_wbig[NKI*256*512];
__device__ int   g_rowptr[NN+1];
__device__ int   g_cnt[NN];
__device__ int   g_fill[NN];
__device__ int   g_esrc[EE];
__device__ float g_ewt[EE];
__device__ float g_sum1[CC];
__device__ float g_sum2[CC];
__device__ float g_scale[CC];
__device__ float g_shift[CC];

__constant__ int c_ki_k[NKI] = {0,0,0,0,0,1,1,1,1,2,2,2,3,3,4};
__constant__ int c_ki_i[NKI] = {0,1,2,3,4,0,1,2,3,0,1,2,0,1,0};

__device__ __forceinline__ float lrelu_f(float v){ return v > 0.f ? v : 0.01f*v; }

// ---------------- small utility kernels ----------------
__global__ void k_copy(const float* __restrict__ src, float* __restrict__ dst, int n4){
    int i = blockIdx.x*blockDim.x + threadIdx.x;
    if (i < n4) ((float4*)dst)[i] = ((const float4*)src)[i];
}

__global__ void k_zero_int(){
    for (int i = blockIdx.x*blockDim.x + threadIdx.x; i < NN; i += gridDim.x*blockDim.x){
        g_cnt[i]=0; g_fill[i]=0;
    }
}

__global__ void k_hist(const int* __restrict__ eidx){
    int e = blockIdx.x*blockDim.x + threadIdx.x;
    if (e < EE) atomicAdd(&g_cnt[eidx[EE + e]], 1);
}

// single-block exclusive scan of g_cnt -> g_rowptr (NN+1 entries)
__global__ void k_scan(){
    __shared__ int sm[1024];
    int t = threadIdx.x;
    const int CH = 40;                 // 1024*40 = 40960 >= NN
    int base = t*CH;
    int ps = 0;
    #pragma unroll 4
    for (int j=0;j<CH;j++){ int idx = base+j; if (idx < NN) ps += g_cnt[idx]; }
    sm[t]=ps; __syncthreads();
    for (int off=1; off<1024; off<<=1){
        int v = (t>=off) ? sm[t-off] : 0;
        __syncthreads();
        sm[t] += v;
        __syncthreads();
    }
    int run = sm[t]-ps;
    for (int j=0;j<CH;j++){ int idx=base+j; if (idx<NN){ g_rowptr[idx]=run; run += g_cnt[idx]; } }
    if (t==1023) g_rowptr[NN] = sm[1023];
}

__global__ void k_scatter(const int* __restrict__ eidx, const float* __restrict__ ew){
    int e = blockIdx.x*blockDim.x + threadIdx.x;
    if (e < EE){
        int s = eidx[e];
        int d = eidx[EE+e];
        int pos = g_rowptr[d] + atomicAdd(&g_fill[d],1);
        g_esrc[pos]=s; g_ewt[pos]=ew[e];
    }
}

// ---------------- weight precompute: Wbig[ki] = [[U_rz, U_in, 0],[WhhT_rz, 0, WhhT_hn]] ----------------
// Wbig layout: [256 K-rows][512 cols], row-major. Cols: 0:128 r, 128:256 z, 256:384 i_n, 384:512 h_n.
__global__ void k_build_u(const float* __restrict__ convw, const float* __restrict__ wih){
    int ki = blockIdx.x, r = blockIdx.y, t = threadIdx.x;
    int k = c_ki_k[ki], i = c_ki_i[ki];
    __shared__ float wrow[CC];
    wrow[t] = convw[((k*5+i)*CC + r)*CC + t];
    __syncthreads();
    float* outb = g_wbig + ki*256*512 + r*512;
    #pragma unroll
    for (int m=0; m<3; m++){
        int cidx = t + m*CC;
        const float* wr = wih + (k*384 + cidx)*CC;
        float s = 0.f;
        #pragma unroll 8
        for (int j=0;j<CC;j++) s += wrow[j]*wr[j];
        outb[cidx] = s;               // U[r][cidx]: cols 0..383
    }
    outb[384+t] = 0.f;                // h_n region has no agg contribution
}

__global__ void k_build_whh(const float* __restrict__ whh){
    int ki = blockIdx.x, jr = blockIdx.y, t = threadIdx.x;
    int k = c_ki_k[ki];
    float* outb = g_wbig + ki*256*512 + (128+jr)*512;
    outb[t]       = whh[(k*384 + t)*CC + jr];        // r cols
    outb[128+t]   = whh[(k*384 + 128 + t)*CC + jr];  // z cols
    outb[256+t]   = 0.f;                             // i_n has no h contribution
    outb[384+t]   = whh[(k*384 + 256 + t)*CC + jr];  // h_n cols
}

// ---------------- CSR aggregation: agg = A @ x (warp per node) ----------------
__global__ void k_agg(const float* __restrict__ xin, int useW){
    int node = blockIdx.x*8 + (threadIdx.x>>5);
    int lane = threadIdx.x & 31;
    int beg = g_rowptr[node], end = g_rowptr[node+1];
    float4 acc = make_float4(0.f,0.f,0.f,0.f);
    for (int j=beg; j<end; j++){
        int s = g_esrc[j];
        float w = useW ? g_ewt[j] : 1.0f;
        float4 v = *(const float4*)(xin + s*CC + lane*4);
        acc.x += w*v.x; acc.y += w*v.y; acc.z += w*v.z; acc.w += w*v.w;
    }
    *(float4*)(g_agg + node*CC + lane*4) = acc;
}

// ---------------- fused GRU GEMM: [agg|x] @ Wbig + GRU epilogue ----------------
// grid (313, 4); block 256. Tile: 128 rows x 32 channels, 4 gate groups per channel.
__global__ void __launch_bounds__(256) k_gru(
    const float* __restrict__ xin, float* __restrict__ xout,
    const float* __restrict__ wbig,
    const float* __restrict__ bih, const float* __restrict__ bhh)
{
    __shared__ float As[8][128];
    __shared__ float Ws[8][128];
    int tx = threadIdx.x;
    int tileM = blockIdx.x * 128;
    int cb = blockIdx.y;                    // channel block 0..3 (32 channels each)
    int rg = tx >> 4, cg = tx & 15;
    int r0 = rg*8, c0 = cg*2;

    float acc[8][4][2];
    #pragma unroll
    for (int j=0;j<8;j++)
        #pragma unroll
        for (int g=0;g<4;g++){ acc[j][g][0]=0.f; acc[j][g][1]=0.f; }

    int la_row = tx >> 1;
    int la_kq  = (tx & 1)*4;
    int lw_kk  = tx >> 5;
    int lw_g   = (tx & 31) >> 3;
    int lw_c4  = (tx & 7)*4;

    for (int kt=0; kt<32; kt++){
        int k0 = kt*8;
        const float* Ag = (kt<16) ? g_agg : xin;
        int kk0 = (kt<16) ? k0 : (k0-128);
        int grow = tileM + la_row;
        float4 av = make_float4(0.f,0.f,0.f,0.f);
        if (grow < NN) av = *(const float4*)(Ag + grow*CC + kk0 + la_kq);
        As[la_kq+0][la_row]=av.x; As[la_kq+1][la_row]=av.y;
        As[la_kq+2][la_row]=av.z; As[la_kq+3][la_row]=av.w;
        float4 wv = *(const float4*)(wbig + (k0+lw_kk)*512 + lw_g*128 + cb*32 + lw_c4);
        *(float4*)&Ws[lw_kk][lw_g*32 + lw_c4] = wv;
        __syncthreads();

        if (kt < 16){
            // agg half: groups r, z, i_n
            #pragma unroll
            for (int kk=0;kk<8;kk++){
                float a[8];
                #pragma unroll
                for (int j=0;j<8;j++) a[j] = As[kk][r0+j];
                float w0a=Ws[kk][c0],    w0b=Ws[kk][c0+1];
                float w1a=Ws[kk][32+c0], w1b=Ws[kk][32+c0+1];
                float w2a=Ws[kk][64+c0], w2b=Ws[kk][64+c0+1];
                #pragma unroll
                for (int j=0;j<8;j++){
                    acc[j][0][0] += a[j]*w0a; acc[j][0][1] += a[j]*w0b;
                    acc[j][1][0] += a[j]*w1a; acc[j][1][1] += a[j]*w1b;
                    acc[j][2][0] += a[j]*w2a; acc[j][2][1] += a[j]*w2b;
                }
            }
        } else {
            // x half: groups r, z, h_n
            #pragma unroll
            for (int kk=0;kk<8;kk++){
                float a[8];
                #pragma unroll
                for (int j=0;j<8;j++) a[j] = As[kk][r0+j];
                float w0a=Ws[kk][c0],    w0b=Ws[kk][c0+1];
                float w1a=Ws[kk][32+c0], w1b=Ws[kk][32+c0+1];
                float w3a=Ws[kk][96+c0], w3b=Ws[kk][96+c0+1];
                #pragma unroll
                for (int j=0;j<8;j++){
                    acc[j][0][0] += a[j]*w0a; acc[j][0][1] += a[j]*w0b;
                    acc[j][1][0] += a[j]*w1a; acc[j][1][1] += a[j]*w1b;
                    acc[j][3][0] += a[j]*w3a; acc[j][3][1] += a[j]*w3b;
                }
            }
        }
        __syncthreads();
    }

    // GRU epilogue
    int chan = cb*32 + c0;
    #pragma unroll
    for (int j=0;j<8;j++){
        int row = tileM + r0 + j;
        if (row < NN){
            #pragma unroll
            for (int cc=0; cc<2; cc++){
                int c = chan + cc;
                float sr = acc[j][0][cc] + bih[c]     + bhh[c];
                float sz = acc[j][1][cc] + bih[128+c] + bhh[128+c];
                float si = acc[j][2][cc] + bih[256+c];
                float sh = acc[j][3][cc] + bhh[256+c];
                float r = 1.f/(1.f+expf(-sr));
                float z = 1.f/(1.f+expf(-sz));
                float n = tanhf(si + r*sh);
                float h = xin[row*CC + c];
                xout[row*CC + c] = (1.f-z)*n + z*h;
            }
        }
    }
}

// ---------------- GraphNorm (over all nodes) ----------------
__global__ void k_gn_zero(){
    int t = threadIdx.x; g_sum1[t]=0.f; g_sum2[t]=0.f;
}

__global__ void k_gn_reduce(const float* __restrict__ x, int pre){
    __shared__ float s1[256], s2[256];
    int t = threadIdx.x;
    int c = t & 127, half = t >> 7;
    float a=0.f, b=0.f;
    for (int row = blockIdx.x*2 + half; row < NN; row += gridDim.x*2){
        float v = x[row*CC + c];
        if (pre) v = lrelu_f(v);
        a += v; b += v*v;
    }
    s1[t]=a; s2[t]=b; __syncthreads();
    if (t < 128){
        a = s1[t]+s1[t+128]; b = s2[t]+s2[t+128];
        atomicAdd(&g_sum1[c], a); atomicAdd(&g_sum2[c], b);
    }
}

__global__ void k_gn_final(const float* __restrict__ w, const float* __restrict__ bb,
                           const float* __restrict__ ms){
    int c = threadIdx.x;
    float inv = 1.f/(float)NN;
    float mean = g_sum1[c]*inv;
    float ex2  = g_sum2[c]*inv;
    float msm  = ms[c]*mean;
    float var  = ex2 - 2.f*msm*mean + msm*msm;   // E[(x - ms*mean)^2]
    float sc   = w[c]/sqrtf(var + 1e-5f);
    g_scale[c]=sc; g_shift[c]=bb[c] - sc*msm;
}

__global__ void k_gn_apply(float* __restrict__ x, int pre, int post){
    int i = blockIdx.x*blockDim.x + threadIdx.x;   // float4 index
    if (i >= NN*CC/4) return;
    int ci = (i & 31)*4;
    float4 v = ((float4*)x)[i];
    float vv[4] = {v.x, v.y, v.z, v.w};
    #pragma unroll
    for (int q=0;q<4;q++){
        float t = vv[q];
        if (pre) t = lrelu_f(t);
        t = g_scale[ci+q]*t + g_shift[ci+q];
        if (post) t = lrelu_f(t);
        vv[q]=t;
    }
    ((float4*)x)[i] = make_float4(vv[0],vv[1],vv[2],vv[3]);
}

// ---------------- final: out[g] = sum over nodes in graph g of lrelu(x) ----------------
__global__ void k_out_zero(float* out){
    int i = blockIdx.x*blockDim.x + threadIdx.x;
    if (i < GG*CC) out[i]=0.f;
}

__global__ void k_final(const float* __restrict__ x, const int* __restrict__ batch,
                        float* __restrict__ out){
    int i = blockIdx.x*blockDim.x + threadIdx.x;
    if (i >= NN*CC) return;
    int row = i >> 7, c = i & 127;
    float v = lrelu_f(x[i]);
    int b = batch[row];
    atomicAdd(&out[b*CC + c], v);
}

// ---------------- host launch ----------------
extern "C" void kernel_launch(void* const* d_in, const int* in_sizes, int n_in,
                              void* d_out, int out_size){
    const float* x_in  = (const float*)d_in[0];
    const float* ew    = (const float*)d_in[1];
    const float* convw = (const float*)d_in[2];
    const float* wih   = (const float*)d_in[3];
    const float* whh   = (const float*)d_in[4];
    const float* bih   = (const float*)d_in[5];
    const float* bhh   = (const float*)d_in[6];
    const float* gnw   = (const float*)d_in[7];
    const float* gnb   = (const float*)d_in[8];
    const float* gnms  = (const float*)d_in[9];
    const int* eidx    = (const int*)d_in[10];   // int32: JAX default config downcasts int64
    const int* batch   = (const int*)d_in[11];   // int32
    float* out = (float*)d_out;

    float *xA, *xB, *wbig;
    cudaGetSymbolAddress((void**)&xA,   g_xA);
    cudaGetSymbolAddress((void**)&xB,   g_xB);
    cudaGetSymbolAddress((void**)&wbig, g_wbig);

    // init + CSR build + weight precompute
    k_copy<<<5000,256>>>(x_in, xA, NN*CC/4);
    k_zero_int<<<256,256>>>();
    k_hist<<<2500,256>>>(eidx);
    k_scan<<<1,1024>>>();
    k_scatter<<<2500,256>>>(eidx, ew);
    k_build_u<<<dim3(NKI,128),128>>>(convw, wih);
    k_build_whh<<<dim3(NKI,128),128>>>(whh);

    const int steps[5]={5,4,3,2,1};
    float* cur=xA; float* nxt=xB;
    int ki=0;
    for (int k=0;k<5;k++){
        for (int i=0;i<steps[k];i++){
            k_agg<<<5000,256>>>(cur, (k<4)?1:0);
            k_gru<<<dim3(313,4),256>>>(cur, nxt, wbig + (size_t)ki*256*512,
                                       bih + k*384, bhh + k*384);
            float* tmp=cur; cur=nxt; nxt=tmp;
            ki++;
        }
        if (k<4){
            int pre  = (k==0)?0:1;
            int post = (k==0)?1:0;
            k_gn_zero<<<1,128>>>();
            k_gn_reduce<<<256,256>>>(cur, pre);
            k_gn_final<<<1,128>>>(gnw + k*CC, gnb + k*CC, gnms + k*CC);
            k_gn_apply<<<5000,256>>>(cur, pre, post);
        }
    }
    k_out_zero<<<32,256>>>(out);
    k_final<<<20000,256>>>(cur, batch, out);
}

// round 5
// speedup vs baseline: 2.0576x; 2.0576x over previous
#include <cuda_runtime.h>
#include <math.h>
#include <stdint.h>

#define NN 40000
#define CC 128
#define EE 640000
#define GG 64
#define NKI 15

// ---------------- device scratch ----------------
__device__ float g_xA[NN*CC];
__device__ float g_xB[NN*CC];
__device__ float g_agg[NN*CC];
__device__ float g_wt[NKI*512*256];     // fused weights, [c=gate*128+chan][k], tf32-rounded
__device__ int   g_rowptr[NN+1];
__device__ int   g_cnt[NN];
__device__ int   g_fill[NN];
__device__ int   g_esrc[EE];
__device__ float g_ewt[EE];
__device__ float g_sum1[CC];
__device__ float g_sum2[CC];
__device__ float g_scale[CC];
__device__ float g_shift[CC];

__constant__ int c_ki_k[NKI] = {0,0,0,0,0,1,1,1,1,2,2,2,3,3,4};
__constant__ int c_ki_i[NKI] = {0,1,2,3,4,0,1,2,3,0,1,2,0,1,0};

__device__ __forceinline__ float lrelu_f(float v){ return v > 0.f ? v : 0.01f*v; }

static __device__ __forceinline__ uint32_t tf32bits(float x){
    uint32_t r; asm("cvt.rna.tf32.f32 %0, %1;" : "=r"(r) : "f"(x)); return r;
}

// ---------------- small utility kernels ----------------
__global__ void k_copy(const float* __restrict__ src, float* __restrict__ dst, int n4){
    int i = blockIdx.x*blockDim.x + threadIdx.x;
    if (i < n4) ((float4*)dst)[i] = ((const float4*)src)[i];
}
__global__ void k_zero_int(){
    for (int i = blockIdx.x*blockDim.x + threadIdx.x; i < NN; i += gridDim.x*blockDim.x){
        g_cnt[i]=0; g_fill[i]=0;
    }
}
__global__ void k_hist(const int* __restrict__ eidx){
    int e = blockIdx.x*blockDim.x + threadIdx.x;
    if (e < EE) atomicAdd(&g_cnt[eidx[EE + e]], 1);
}
__global__ void k_scan(){
    __shared__ int sm[1024];
    int t = threadIdx.x;
    const int CH = 40;
    int base = t*CH;
    int ps = 0;
    #pragma unroll 4
    for (int j=0;j<CH;j++){ int idx = base+j; if (idx < NN) ps += g_cnt[idx]; }
    sm[t]=ps; __syncthreads();
    for (int off=1; off<1024; off<<=1){
        int v = (t>=off) ? sm[t-off] : 0;
        __syncthreads();
        sm[t] += v;
        __syncthreads();
    }
    int run = sm[t]-ps;
    for (int j=0;j<CH;j++){ int idx=base+j; if (idx<NN){ g_rowptr[idx]=run; run += g_cnt[idx]; } }
    if (t==1023) g_rowptr[NN] = sm[1023];
}
__global__ void k_scatter(const int* __restrict__ eidx, const float* __restrict__ ew){
    int e = blockIdx.x*blockDim.x + threadIdx.x;
    if (e < EE){
        int s = eidx[e];
        int d = eidx[EE+e];
        int pos = g_rowptr[d] + atomicAdd(&g_fill[d],1);
        g_esrc[pos]=s; g_ewt[pos]=ew[e];
    }
}

// ---------------- weight precompute: Wt[ki][c][kk] (c=gate col 0..511, kk 0..255) ----------------
// kk<128: agg half = U[kk][c] (U = W_i * wih^T), zero for c>=384 (h_n)
// kk>=128: x half  = whh[c'][kk-128], zero for 256<=c<384 (i_n)
__global__ void k_build_wt(const float* __restrict__ convw, const float* __restrict__ wih,
                           const float* __restrict__ whh){
    int ki = blockIdx.x, c = blockIdx.y, t = threadIdx.x;
    int k = c_ki_k[ki], i = c_ki_i[ki];
    __shared__ float wr[CC];
    float aggv = 0.f;
    if (c < 384){
        wr[t] = wih[(k*384 + c)*CC + t];
        __syncthreads();
        const float* Wrow = convw + ((size_t)((k*5+i)*CC + t))*CC;
        float s = 0.f;
        #pragma unroll 8
        for (int q=0;q<CC;q++) s += Wrow[q]*wr[q];
        aggv = s;
    }
    float xv = 0.f;
    if (c < 256)       xv = whh[(k*384 + c)*CC + t];
    else if (c >= 384) xv = whh[(k*384 + 256 + (c-384))*CC + t];
    float* o = g_wt + ((size_t)ki*512 + c)*256;
    o[t]     = __uint_as_float(tf32bits(aggv));
    o[128+t] = __uint_as_float(tf32bits(xv));
}

// ---------------- CSR aggregation: agg = A @ x (warp per node) ----------------
__global__ void k_agg(const float* __restrict__ xin, int useW){
    int node = blockIdx.x*8 + (threadIdx.x>>5);
    int lane = threadIdx.x & 31;
    int beg = g_rowptr[node], end = g_rowptr[node+1];
    float4 acc = make_float4(0.f,0.f,0.f,0.f);
    for (int j=beg; j<end; j++){
        int s = g_esrc[j];
        float w = useW ? g_ewt[j] : 1.0f;
        float4 v = *(const float4*)(xin + (size_t)s*CC + lane*4);
        acc.x += w*v.x; acc.y += w*v.y; acc.z += w*v.z; acc.w += w*v.w;
    }
    *(float4*)(g_agg + (size_t)node*CC + lane*4) = acc;
}

// ---------------- mma.sync tf32 fused GRU GEMM ----------------
// grid (313,4), block 256 (8 warps). CTA tile: 128 rows x (32 chans x 4 gates = 128 cols).
// K = 256: k<128 from g_agg, k>=128 from xin. Chunks of 32, single-buffered SMEM.
// Warp tile 64x32: wm = wid&1 (row half), wn = wid>>1 (gate). mma m16n8k8 tf32.
#define KCP 36
__global__ void __launch_bounds__(256) k_gru_mma(
    const float* __restrict__ xin, float* __restrict__ xout, int ki,
    const float* __restrict__ bih, const float* __restrict__ bhh)
{
    extern __shared__ uint32_t smem[];
    uint32_t* As = smem;                 // [128][KCP]
    uint32_t* Ws = smem + 128*KCP;       // [128][KCP]
    float*    Cs = (float*)smem;         // [128][136] (reused after GEMM)

    int tx = threadIdx.x;
    int wid = tx >> 5, l = tx & 31;
    int wm = wid & 1, wn = wid >> 1;
    int tileM = blockIdx.x * 128;
    int cb = blockIdx.y;
    const float* wt = g_wt + (size_t)ki*512*256;

    float acc[4][4][4];
    #pragma unroll
    for (int mt=0;mt<4;mt++)
        #pragma unroll
        for (int nt=0;nt<4;nt++){
            acc[mt][nt][0]=0.f; acc[mt][nt][1]=0.f; acc[mt][nt][2]=0.f; acc[mt][nt][3]=0.f;
        }

    for (int chunk=0; chunk<8; chunk++){
        int k0 = chunk*32;
        const float* src = (chunk < 4) ? g_agg : xin;
        int koff = k0 & 127;
        __syncthreads();
        // load A chunk (tf32 convert)
        #pragma unroll
        for (int it=0; it<4; it++){
            int idx = it*256 + tx;           // float4 slot 0..1023
            int r  = idx >> 3;
            int kq = (idx & 7) << 2;
            float4 v = make_float4(0.f,0.f,0.f,0.f);
            int grow = tileM + r;
            if (grow < NN) v = *(const float4*)&src[(size_t)grow*CC + koff + kq];
            uint4 u = make_uint4(tf32bits(v.x), tf32bits(v.y), tf32bits(v.z), tf32bits(v.w));
            *(uint4*)&As[r*KCP + kq] = u;
        }
        // load W chunk (already tf32): local col = gate*32 + chan
        #pragma unroll
        for (int it=0; it<4; it++){
            int idx = it*256 + tx;
            int cl = idx >> 3;
            int kq = (idx & 7) << 2;
            int g = cl >> 5, j = cl & 31;
            uint4 u = *(const uint4*)&wt[(size_t)(g*128 + cb*32 + j)*256 + k0 + kq];
            *(uint4*)&Ws[cl*KCP + kq] = u;
        }
        __syncthreads();

        #pragma unroll
        for (int ks=0; ks<4; ks++){
            int kc = ks*8;
            uint32_t a[4][4];
            #pragma unroll
            for (int mt=0; mt<4; mt++){
                int rb = wm*64 + mt*16 + (l>>2);
                a[mt][0] = As[rb*KCP     + kc + (l&3)];
                a[mt][1] = As[(rb+8)*KCP + kc + (l&3)];
                a[mt][2] = As[rb*KCP     + kc + (l&3) + 4];
                a[mt][3] = As[(rb+8)*KCP + kc + (l&3) + 4];
            }
            uint32_t b[4][2];
            #pragma unroll
            for (int nt=0; nt<4; nt++){
                int nb = wn*32 + nt*8 + (l>>2);
                b[nt][0] = Ws[nb*KCP + kc + (l&3)];
                b[nt][1] = Ws[nb*KCP + kc + (l&3) + 4];
            }
            #pragma unroll
            for (int mt=0; mt<4; mt++)
                #pragma unroll
                for (int nt=0; nt<4; nt++){
                    asm volatile(
                        "mma.sync.aligned.m16n8k8.row.col.f32.tf32.tf32.f32 "
                        "{%0,%1,%2,%3}, {%4,%5,%6,%7}, {%8,%9}, {%0,%1,%2,%3};"
                        : "+f"(acc[mt][nt][0]), "+f"(acc[mt][nt][1]),
                          "+f"(acc[mt][nt][2]), "+f"(acc[mt][nt][3])
                        : "r"(a[mt][0]), "r"(a[mt][1]), "r"(a[mt][2]), "r"(a[mt][3]),
                          "r"(b[nt][0]), "r"(b[nt][1]));
                }
        }
    }

    // ---- write accumulators to Cs [128][136] ----
    __syncthreads();
    #pragma unroll
    for (int mt=0; mt<4; mt++){
        int r0 = wm*64 + mt*16 + (l>>2);
        #pragma unroll
        for (int nt=0; nt<4; nt++){
            int c0 = wn*32 + nt*8 + (l&3)*2;
            *(float2*)&Cs[r0*136 + c0]     = make_float2(acc[mt][nt][0], acc[mt][nt][1]);
            *(float2*)&Cs[(r0+8)*136 + c0] = make_float2(acc[mt][nt][2], acc[mt][nt][3]);
        }
    }
    __syncthreads();

    // ---- GRU epilogue: thread = (warp row group, lane channel) ----
    int j = l;                       // channel 0..31 within cb block
    int c = cb*32 + j;               // global channel
    float b_r = bih[c] + bhh[c];
    float b_z = bih[128+c] + bhh[128+c];
    float b_i = bih[256+c];
    float b_h = bhh[256+c];
    #pragma unroll
    for (int rr=0; rr<16; rr++){
        int lrow = wid*16 + rr;
        int row = tileM + lrow;
        if (row < NN){
            float sr = Cs[lrow*136 + j]      + b_r;
            float sz = Cs[lrow*136 + 32 + j] + b_z;
            float si = Cs[lrow*136 + 64 + j] + b_i;
            float sh = Cs[lrow*136 + 96 + j] + b_h;
            float r = 1.f/(1.f+expf(-sr));
            float z = 1.f/(1.f+expf(-sz));
            float n = tanhf(si + r*sh);
            float h = xin[(size_t)row*CC + c];
            xout[(size_t)row*CC + c] = (1.f-z)*n + z*h;
        }
    }
}

// ---------------- GraphNorm ----------------
__global__ void k_gn_zero(){
    int t = threadIdx.x; g_sum1[t]=0.f; g_sum2[t]=0.f;
}
__global__ void k_gn_reduce(const float* __restrict__ x, int pre){
    __shared__ float s1[256], s2[256];
    int t = threadIdx.x;
    int c = t & 127, half = t >> 7;
    float a=0.f, b=0.f;
    for (int row = blockIdx.x*2 + half; row < NN; row += gridDim.x*2){
        float v = x[(size_t)row*CC + c];
        if (pre) v = lrelu_f(v);
        a += v; b += v*v;
    }
    s1[t]=a; s2[t]=b; __syncthreads();
    if (t < 128){
        a = s1[t]+s1[t+128]; b = s2[t]+s2[t+128];
        atomicAdd(&g_sum1[c], a); atomicAdd(&g_sum2[c], b);
    }
}
__global__ void k_gn_final(const float* __restrict__ w, const float* __restrict__ bb,
                           const float* __restrict__ ms){
    int c = threadIdx.x;
    float inv = 1.f/(float)NN;
    float mean = g_sum1[c]*inv;
    float ex2  = g_sum2[c]*inv;
    float msm  = ms[c]*mean;
    float var  = ex2 - 2.f*msm*mean + msm*msm;
    float sc   = w[c]/sqrtf(var + 1e-5f);
    g_scale[c]=sc; g_shift[c]=bb[c] - sc*msm;
}
__global__ void k_gn_apply(float* __restrict__ x, int pre, int post){
    int i = blockIdx.x*blockDim.x + threadIdx.x;
    if (i >= NN*CC/4) return;
    int ci = (i & 31)*4;
    float4 v = ((float4*)x)[i];
    float vv[4] = {v.x, v.y, v.z, v.w};
    #pragma unroll
    for (int q=0;q<4;q++){
        float t = vv[q];
        if (pre) t = lrelu_f(t);
        t = g_scale[ci+q]*t + g_shift[ci+q];
        if (post) t = lrelu_f(t);
        vv[q]=t;
    }
    ((float4*)x)[i] = make_float4(vv[0],vv[1],vv[2],vv[3]);
}

// ---------------- final segment-sum ----------------
__global__ void k_out_zero(float* out){
    int i = blockIdx.x*blockDim.x + threadIdx.x;
    if (i < GG*CC) out[i]=0.f;
}
__global__ void k_final(const float* __restrict__ x, const int* __restrict__ batch,
                        float* __restrict__ out){
    int i = blockIdx.x*blockDim.x + threadIdx.x;
    if (i >= NN*CC) return;
    int row = i >> 7, c = i & 127;
    float v = lrelu_f(x[i]);
    int b = batch[row];
    atomicAdd(&out[b*CC + c], v);
}

// ---------------- host launch ----------------
extern "C" void kernel_launch(void* const* d_in, const int* in_sizes, int n_in,
                              void* d_out, int out_size){
    const float* x_in  = (const float*)d_in[0];
    const float* ew    = (const float*)d_in[1];
    const float* convw = (const float*)d_in[2];
    const float* wih   = (const float*)d_in[3];
    const float* whh   = (const float*)d_in[4];
    const float* bih   = (const float*)d_in[5];
    const float* bhh   = (const float*)d_in[6];
    const float* gnw   = (const float*)d_in[7];
    const float* gnb   = (const float*)d_in[8];
    const float* gnms  = (const float*)d_in[9];
    const int* eidx    = (const int*)d_in[10];
    const int* batch   = (const int*)d_in[11];
    float* out = (float*)d_out;

    float *xA, *xB;
    cudaGetSymbolAddress((void**)&xA, g_xA);
    cudaGetSymbolAddress((void**)&xB, g_xB);

    const int smem_gru = 128*136*4;   // 69632 B (Cs; covers As+Ws)
    static int s_attr_done = 0;
    if (!s_attr_done){
        cudaFuncSetAttribute(k_gru_mma, cudaFuncAttributeMaxDynamicSharedMemorySize, smem_gru);
        s_attr_done = 1;
    }

    k_copy<<<5000,256>>>(x_in, xA, NN*CC/4);
    k_zero_int<<<256,256>>>();
    k_hist<<<2500,256>>>(eidx);
    k_scan<<<1,1024>>>();
    k_scatter<<<2500,256>>>(eidx, ew);
    k_build_wt<<<dim3(NKI,512),128>>>(convw, wih, whh);

    const int steps[5]={5,4,3,2,1};
    float* cur=xA; float* nxt=xB;
    int ki=0;
    for (int k=0;k<5;k++){
        for (int i=0;i<steps[k];i++){
            k_agg<<<5000,256>>>(cur, (k<4)?1:0);
            k_gru_mma<<<dim3(313,4),256,smem_gru>>>(cur, nxt, ki, bih + k*384, bhh + k*384);
            float* tmp=cur; cur=nxt; nxt=tmp;
            ki++;
        }
        if (k<4){
            int pre  = (k==0)?0:1;
            int post = (k==0)?1:0;
            k_gn_zero<<<1,128>>>();
            k_gn_reduce<<<256,256>>>(cur, pre);
            k_gn_final<<<1,128>>>(gnw + k*CC, gnb + k*CC, gnms + k*CC);
            k_gn_apply<<<5000,256>>>(cur, pre, post);
        }
    }
    k_out_zero<<<32,256>>>(out);
    k_final<<<20000,256>>>(cur, batch, out);
}

// round 7
// speedup vs baseline: 2.2248x; 1.0813x over previous
#include <cuda_runtime.h>
#include <math.h>
#include <stdint.h>

#define NN 40000
#define CC 128
#define EE 640000
#define GG 64
#define NKI 15
#define SCB 157   // scan blocks of 256: 157*256 >= NN

// ---------------- device scratch ----------------
__device__ float g_xA[NN*CC];
__device__ float g_xB[NN*CC];
__device__ float g_agg[NN*CC];
__device__ float g_wt[NKI*512*256];     // fused weights, [c=gate*128+chan][k], tf32-rounded
__device__ int   g_rowptr[NN+1];
__device__ int   g_cnt[NN];
__device__ int   g_fill[NN];
__device__ int   g_esrc[EE];
__device__ float g_ewt[EE];
__device__ int   g_bsum[256];
__device__ int   g_boff[256];
__device__ float g_sum1[CC];
__device__ float g_sum2[CC];
__device__ float g_scale[CC];
__device__ float g_shift[CC];

__constant__ int c_ki_k[NKI] = {0,0,0,0,0,1,1,1,1,2,2,2,3,3,4};
__constant__ int c_ki_i[NKI] = {0,1,2,3,4,0,1,2,3,0,1,2,0,1,0};

__device__ __forceinline__ float lrelu_f(float v){ return v > 0.f ? v : 0.01f*v; }

static __device__ __forceinline__ uint32_t tf32bits(float x){
    uint32_t r; asm("cvt.rna.tf32.f32 %0, %1;" : "=r"(r) : "f"(x)); return r;
}
static __device__ __forceinline__ uint32_t smem_u32(const void* p){
    uint32_t a;
    asm("{ .reg .u64 t; cvta.to.shared.u64 t, %1; cvt.u32.u64 %0, t; }" : "=r"(a) : "l"(p));
    return a;
}

// ---------------- small utility kernels ----------------
__global__ void k_copy(const float* __restrict__ src, float* __restrict__ dst, int n4){
    int i = blockIdx.x*blockDim.x + threadIdx.x;
    if (i < n4) ((float4*)dst)[i] = ((const float4*)src)[i];
}
__global__ void k_zero_int(){
    for (int i = blockIdx.x*blockDim.x + threadIdx.x; i < NN; i += gridDim.x*blockDim.x){
        g_cnt[i]=0; g_fill[i]=0;
    }
}
__global__ void k_hist(const int* __restrict__ eidx){
    int e = blockIdx.x*blockDim.x + threadIdx.x;
    if (e < EE) atomicAdd(&g_cnt[eidx[EE + e]], 1);
}
// ---- parallel 3-phase exclusive scan of g_cnt -> g_rowptr ----
__global__ void k_scan1(){
    __shared__ int sm[256];
    int t = threadIdx.x;
    int i = blockIdx.x*256 + t;
    int v = (i < NN) ? g_cnt[i] : 0;
    sm[t] = v; __syncthreads();
    #pragma unroll
    for (int off=1; off<256; off<<=1){
        int nv = (t>=off) ? sm[t-off] : 0;
        __syncthreads();
        sm[t] += nv;
        __syncthreads();
    }
    if (i < NN) g_rowptr[i] = sm[t] - v;
    if (t == 255) g_bsum[blockIdx.x] = sm[255];
}
__global__ void k_scan2(){
    __shared__ int sm[256];
    int t = threadIdx.x;
    int v = (t < SCB) ? g_bsum[t] : 0;
    sm[t] = v; __syncthreads();
    #pragma unroll
    for (int off=1; off<256; off<<=1){
        int nv = (t>=off) ? sm[t-off] : 0;
        __syncthreads();
        sm[t] += nv;
        __syncthreads();
    }
    g_boff[t] = sm[t] - v;
}
__global__ void k_scan3(){
    int t = threadIdx.x;
    int i = blockIdx.x*256 + t;
    if (i < NN) g_rowptr[i] += g_boff[blockIdx.x];
    if (i == 0) g_rowptr[NN] = EE;
}
__global__ void k_scatter(const int* __restrict__ eidx, const float* __restrict__ ew){
    int e = blockIdx.x*blockDim.x + threadIdx.x;
    if (e < EE){
        int s = eidx[e];
        int d = eidx[EE+e];
        int pos = g_rowptr[d] + atomicAdd(&g_fill[d],1);
        g_esrc[pos]=s; g_ewt[pos]=ew[e];
    }
}

// ---------------- weight precompute: Wt[ki][c][kk] (c=gate col 0..511, kk 0..255) ----------------
__global__ void k_build_wt(const float* __restrict__ convw, const float* __restrict__ wih,
                           const float* __restrict__ whh){
    int ki = blockIdx.x, c = blockIdx.y, t = threadIdx.x;
    int k = c_ki_k[ki], i = c_ki_i[ki];
    __shared__ float wr[CC];
    float aggv = 0.f;
    if (c < 384){
        wr[t] = wih[(k*384 + c)*CC + t];
        __syncthreads();
        const float* Wrow = convw + ((size_t)((k*5+i)*CC + t))*CC;
        float s = 0.f;
        #pragma unroll 8
        for (int q=0;q<CC;q++) s += Wrow[q]*wr[q];
        aggv = s;
    }
    float xv = 0.f;
    if (c < 256)       xv = whh[(k*384 + c)*CC + t];
    else if (c >= 384) xv = whh[(k*384 + 256 + (c-384))*CC + t];
    float* o = g_wt + ((size_t)ki*512 + c)*256;
    o[t]     = __uint_as_float(tf32bits(aggv));
    o[128+t] = __uint_as_float(tf32bits(xv));
}

// ---------------- CSR aggregation: agg = A @ x (warp per node) ----------------
__global__ void k_agg(const float* __restrict__ xin, int useW){
    int node = blockIdx.x*8 + (threadIdx.x>>5);
    int lane = threadIdx.x & 31;
    int beg = g_rowptr[node], end = g_rowptr[node+1];
    float4 acc = make_float4(0.f,0.f,0.f,0.f);
    for (int j=beg; j<end; j++){
        int s = g_esrc[j];
        float w = useW ? g_ewt[j] : 1.0f;
        float4 v = *(const float4*)(xin + (size_t)s*CC + lane*4);
        acc.x += w*v.x; acc.y += w*v.y; acc.z += w*v.z; acc.w += w*v.w;
    }
    *(float4*)(g_agg + (size_t)node*CC + lane*4) = acc;
}

// ---------------- mma.sync tf32 fused GRU GEMM, software-pipelined ----------------
// grid (313,4), block 256 (8 warps). CTA tile: 128 rows x (32 chans x 4 gates = 128 cols).
// K = 256: k<128 from g_agg, k>=128 from xin. 8 chunks of 32, double-buffered.
// B via cp.async; A register-staged (LDG early, STS after mma).
#define KCP 36
#define BUFW (128*KCP)
__global__ void __launch_bounds__(256,2) k_gru_mma(
    const float* __restrict__ xin, float* __restrict__ xout, int ki,
    const float* __restrict__ bih, const float* __restrict__ bhh)
{
    extern __shared__ uint32_t smem[];
    uint32_t* As = smem;                 // [2][128][KCP]
    uint32_t* Ws = smem + 2*BUFW;        // [2][128][KCP]
    float*    Cs = (float*)smem;         // [128][136] (reused after GEMM)

    int tx = threadIdx.x;
    int wid = tx >> 5, l = tx & 31;
    int wm = wid & 1, wn = wid >> 1;
    int tileM = blockIdx.x * 128;
    int cb = blockIdx.y;
    const float* wt = g_wt + (size_t)ki*512*256;
    uint32_t sW = smem_u32(Ws);

    // per-thread load coordinates (A): 4 float4s
    int a_r  = tx >> 3;                  // row slot base (stride 32 rows per it)
    int a_kq = (tx & 7) << 2;
    // per-thread load coordinates (B)
    int b_cl = tx >> 3;
    int b_kq = (tx & 7) << 2;

    float acc[4][4][4];
    #pragma unroll
    for (int mt=0;mt<4;mt++)
        #pragma unroll
        for (int nt=0;nt<4;nt++){
            acc[mt][nt][0]=0.f; acc[mt][nt][1]=0.f; acc[mt][nt][2]=0.f; acc[mt][nt][3]=0.f;
        }

    // ---- prologue: chunk 0 ----
    {
        const float* src = g_agg;
        #pragma unroll
        for (int it=0; it<4; it++){
            int r = a_r + it*32;
            float4 v = make_float4(0.f,0.f,0.f,0.f);
            int grow = tileM + r;
            if (grow < NN) v = *(const float4*)&src[(size_t)grow*CC + a_kq];
            uint4 u = make_uint4(tf32bits(v.x), tf32bits(v.y), tf32bits(v.z), tf32bits(v.w));
            *(uint4*)&As[r*KCP + a_kq] = u;
        }
        #pragma unroll
        for (int it=0; it<4; it++){
            int cl = b_cl + it*32;
            int g = cl >> 5, j = cl & 31;
            const float* gp = &wt[(size_t)(g*128 + cb*32 + j)*256 + b_kq];
            uint32_t sa = sW + (uint32_t)(cl*KCP + b_kq)*4u;
            asm volatile("cp.async.ca.shared.global [%0], [%1], 16;" :: "r"(sa), "l"(gp));
        }
        asm volatile("cp.async.commit_group;" ::: "memory");
    }

    for (int ch=0; ch<8; ch++){
        asm volatile("cp.async.wait_group 0;" ::: "memory");
        __syncthreads();

        int nbuf = (ch+1) & 1;
        float4 va[4];
        if (ch < 7){
            // LDG A(ch+1) into registers now; STS after mma
            const float* src = (ch+1 < 4) ? g_agg : xin;
            int koff = ((ch+1)*32) & 127;
            #pragma unroll
            for (int it=0; it<4; it++){
                int r = a_r + it*32;
                float4 v = make_float4(0.f,0.f,0.f,0.f);
                int grow = tileM + r;
                if (grow < NN) v = *(const float4*)&src[(size_t)grow*CC + koff + a_kq];
                va[it] = v;
            }
            // B(ch+1) via cp.async
            int k0 = (ch+1)*32;
            #pragma unroll
            for (int it=0; it<4; it++){
                int cl = b_cl + it*32;
                int g = cl >> 5, j = cl & 31;
                const float* gp = &wt[(size_t)(g*128 + cb*32 + j)*256 + k0 + b_kq];
                uint32_t sa = sW + (uint32_t)(nbuf*BUFW + cl*KCP + b_kq)*4u;
                asm volatile("cp.async.ca.shared.global [%0], [%1], 16;" :: "r"(sa), "l"(gp));
            }
            asm volatile("cp.async.commit_group;" ::: "memory");
        }

        // ---- mma on buffer ch&1 ----
        uint32_t* Ab = As + (ch&1)*BUFW;
        uint32_t* Wb = Ws + (ch&1)*BUFW;
        #pragma unroll
        for (int ks=0; ks<4; ks++){
            int kc = ks*8;
            uint32_t a[4][4];
            #pragma unroll
            for (int mt=0; mt<4; mt++){
                int rb = wm*64 + mt*16 + (l>>2);
                a[mt][0] = Ab[rb*KCP     + kc + (l&3)];
                a[mt][1] = Ab[(rb+8)*KCP + kc + (l&3)];
                a[mt][2] = Ab[rb*KCP     + kc + (l&3) + 4];
                a[mt][3] = Ab[(rb+8)*KCP + kc + (l&3) + 4];
            }
            uint32_t b[4][2];
            #pragma unroll
            for (int nt=0; nt<4; nt++){
                int nb = wn*32 + nt*8 + (l>>2);
                b[nt][0] = Wb[nb*KCP + kc + (l&3)];
                b[nt][1] = Wb[nb*KCP + kc + (l&3) + 4];
            }
            #pragma unroll
            for (int mt=0; mt<4; mt++)
                #pragma unroll
                for (int nt=0; nt<4; nt++){
                    asm volatile(
                        "mma.sync.aligned.m16n8k8.row.col.f32.tf32.tf32.f32 "
                        "{%0,%1,%2,%3}, {%4,%5,%6,%7}, {%8,%9}, {%0,%1,%2,%3};"
                        : "+f"(acc[mt][nt][0]), "+f"(acc[mt][nt][1]),
                          "+f"(acc[mt][nt][2]), "+f"(acc[mt][nt][3])
                        : "r"(a[mt][0]), "r"(a[mt][1]), "r"(a[mt][2]), "r"(a[mt][3]),
                          "r"(b[nt][0]), "r"(b[nt][1]));
                }
        }

        if (ch < 7){
            // STS A(ch+1) (safe: buffer nbuf readers finished before this iter's sync)
            #pragma unroll
            for (int it=0; it<4; it++){
                int r = a_r + it*32;
                uint4 u = make_uint4(tf32bits(va[it].x), tf32bits(va[it].y),
                                     tf32bits(va[it].z), tf32bits(va[it].w));
                *(uint4*)&As[nbuf*BUFW + r*KCP + a_kq] = u;
            }
        }
    }

    // ---- write accumulators to Cs [128][136] ----
    __syncthreads();
    #pragma unroll
    for (int mt=0; mt<4; mt++){
        int r0 = wm*64 + mt*16 + (l>>2);
        #pragma unroll
        for (int nt=0; nt<4; nt++){
            int c0 = wn*32 + nt*8 + (l&3)*2;
            *(float2*)&Cs[r0*136 + c0]     = make_float2(acc[mt][nt][0], acc[mt][nt][1]);
            *(float2*)&Cs[(r0+8)*136 + c0] = make_float2(acc[mt][nt][2], acc[mt][nt][3]);
        }
    }
    __syncthreads();

    // ---- GRU epilogue ----
    int j = l;
    int c = cb*32 + j;
    float b_r = bih[c] + bhh[c];
    float b_z = bih[128+c] + bhh[128+c];
    float b_i = bih[256+c];
    float b_h = bhh[256+c];
    #pragma unroll
    for (int rr=0; rr<16; rr++){
        int lrow = wid*16 + rr;
        int row = tileM + lrow;
        if (row < NN){
            float sr = Cs[lrow*136 + j]      + b_r;
            float sz = Cs[lrow*136 + 32 + j] + b_z;
            float si = Cs[lrow*136 + 64 + j] + b_i;
            float sh = Cs[lrow*136 + 96 + j] + b_h;
            float r = 1.f/(1.f+expf(-sr));
            float z = 1.f/(1.f+expf(-sz));
            float n = tanhf(si + r*sh);
            float h = xin[(size_t)row*CC + c];
            xout[(size_t)row*CC + c] = (1.f-z)*n + z*h;
        }
    }
}

// ---------------- GraphNorm ----------------
__global__ void k_gn_zero(){
    int t = threadIdx.x; g_sum1[t]=0.f; g_sum2[t]=0.f;
}
__global__ void k_gn_reduce(const float* __restrict__ x, int pre){
    __shared__ float s1[256], s2[256];
    int t = threadIdx.x;
    int c = t & 127, half = t >> 7;
    float a=0.f, b=0.f;
    for (int row = blockIdx.x*2 + half; row < NN; row += gridDim.x*2){
        float v = x[(size_t)row*CC + c];
        if (pre) v = lrelu_f(v);
        a += v; b += v*v;
    }
    s1[t]=a; s2[t]=b; __syncthreads();
    if (t < 128){
        a = s1[t]+s1[t+128]; b = s2[t]+s2[t+128];
        atomicAdd(&g_sum1[c], a); atomicAdd(&g_sum2[c], b);
    }
}
__global__ void k_gn_final(const float* __restrict__ w, const float* __restrict__ bb,
                           const float* __restrict__ ms){
    int c = threadIdx.x;
    float inv = 1.f/(float)NN;
    float mean = g_sum1[c]*inv;
    float ex2  = g_sum2[c]*inv;
    float msm  = ms[c]*mean;
    float var  = ex2 - 2.f*msm*mean + msm*msm;
    float sc   = w[c]/sqrtf(var + 1e-5f);
    g_scale[c]=sc; g_shift[c]=bb[c] - sc*msm;
}
__global__ void k_gn_apply(float* __restrict__ x, int pre, int post){
    int i = blockIdx.x*blockDim.x + threadIdx.x;
    if (i >= NN*CC/4) return;
    int ci = (i & 31)*4;
    float4 v = ((float4*)x)[i];
    float vv[4] = {v.x, v.y, v.z, v.w};
    #pragma unroll
    for (int q=0;q<4;q++){
        float t = vv[q];
        if (pre) t = lrelu_f(t);
        t = g_scale[ci+q]*t + g_shift[ci+q];
        if (post) t = lrelu_f(t);
        vv[q]=t;
    }
    ((float4*)x)[i] = make_float4(vv[0],vv[1],vv[2],vv[3]);
}

// ---------------- final segment-sum ----------------
__global__ void k_out_zero(float* out){
    int i = blockIdx.x*blockDim.x + threadIdx.x;
    if (i < GG*CC) out[i]=0.f;
}
__global__ void k_final(const float* __restrict__ x, const int* __restrict__ batch,
                        float* __restrict__ out){
    int i = blockIdx.x*blockDim.x + threadIdx.x;
    if (i >= NN*CC) return;
    int row = i >> 7, c = i & 127;
    float v = lrelu_f(x[i]);
    int b = batch[row];
    atomicAdd(&out[b*CC + c], v);
}

// ---------------- host launch ----------------
extern "C" void kernel_launch(void* const* d_in, const int* in_sizes, int n_in,
                              void* d_out, int out_size){
    const float* x_in  = (const float*)d_in[0];
    const float* ew    = (const float*)d_in[1];
    const float* convw = (const float*)d_in[2];
    const float* wih   = (const float*)d_in[3];
    const float* whh   = (const float*)d_in[4];
    const float* bih   = (const float*)d_in[5];
    const float* bhh   = (const float*)d_in[6];
    const float* gnw   = (const float*)d_in[7];
    const float* gnb   = (const float*)d_in[8];
    const float* gnms  = (const float*)d_in[9];
    const int* eidx    = (const int*)d_in[10];
    const int* batch   = (const int*)d_in[11];
    float* out = (float*)d_out;

    float *xA, *xB;
    cudaGetSymbolAddress((void**)&xA, g_xA);
    cudaGetSymbolAddress((void**)&xB, g_xB);

    const int smem_gru = 4*BUFW*4;    // 73728 B (2xA + 2xB buffers; covers Cs 69632)
    static int s_attr_done = 0;
    if (!s_attr_done){
        cudaFuncSetAttribute(k_gru_mma, cudaFuncAttributeMaxDynamicSharedMemorySize, smem_gru);
        s_attr_done = 1;
    }

    k_copy<<<5000,256>>>(x_in, xA, NN*CC/4);
    k_zero_int<<<256,256>>>();
    k_hist<<<2500,256>>>(eidx);
    k_scan1<<<SCB,256>>>();
    k_scan2<<<1,256>>>();
    k_scan3<<<SCB,256>>>();
    k_scatter<<<2500,256>>>(eidx, ew);
    k_build_wt<<<dim3(NKI,512),128>>>(convw, wih, whh);

    const int steps[5]={5,4,3,2,1};
    float* cur=xA; float* nxt=xB;
    int ki=0;
    for (int k=0;k<5;k++){
        for (int i=0;i<steps[k];i++){
            k_agg<<<5000,256>>>(cur, (k<4)?1:0);
            k_gru_mma<<<dim3(313,4),256,smem_gru>>>(cur, nxt, ki, bih + k*384, bhh + k*384);
            float* tmp=cur; cur=nxt; nxt=tmp;
            ki++;
        }
        if (k<4){
            int pre  = (k==0)?0:1;
            int post = (k==0)?1:0;
            k_gn_zero<<<1,128>>>();
            k_gn_reduce<<<256,256>>>(cur, pre);
            k_gn_final<<<1,128>>>(gnw + k*CC, gnb + k*CC, gnms + k*CC);
            k_gn_apply<<<5000,256>>>(cur, pre, post);
        }
    }
    k_out_zero<<<32,256>>>(out);
    k_final<<<20000,256>>>(cur, batch, out);
}

// round 10
// speedup vs baseline: 2.2528x; 1.0126x over previous
#include <cuda_runtime.h>
#include <math.h>
#include <stdint.h>

#define NN 40000
#define CC 128
#define EE 640000
#define GG 64
#define NKI 15
#define SCB 157   // scan blocks of 256: 157*256 >= NN

// ---------------- device scratch ----------------
__device__ float g_xA[NN*CC];
__device__ float g_xB[NN*CC];
__device__ float g_agg[NN*CC];
__device__ float g_wt[NKI*512*256];     // fused weights, [c=gate*128+chan][k], tf32-rounded
__device__ int   g_rowptr[NN+1];
__device__ int   g_cnt[NN];
__device__ int   g_fill[NN];
__device__ int   g_esrc[EE];
__device__ float g_ewt[EE];
__device__ int   g_bsum[256];
__device__ int   g_boff[256];
__device__ float g_sum1[CC];
__device__ float g_sum2[CC];
__device__ float g_scale[CC];
__device__ float g_shift[CC];

__constant__ int c_ki_k[NKI] = {0,0,0,0,0,1,1,1,1,2,2,2,3,3,4};
__constant__ int c_ki_i[NKI] = {0,1,2,3,4,0,1,2,3,0,1,2,0,1,0};

__device__ __forceinline__ float lrelu_f(float v){ return v > 0.f ? v : 0.01f*v; }

static __device__ __forceinline__ uint32_t tf32bits(float x){
    uint32_t r; asm("cvt.rna.tf32.f32 %0, %1;" : "=r"(r) : "f"(x)); return r;
}
static __device__ __forceinline__ uint32_t smem_u32(const void* p){
    uint32_t a;
    asm("{ .reg .u64 t; cvta.to.shared.u64 t, %1; cvt.u32.u64 %0, t; }" : "=r"(a) : "l"(p));
    return a;
}

// ---------------- small utility kernels ----------------
__global__ void k_copy(const float* __restrict__ src, float* __restrict__ dst, int n4){
    int i = blockIdx.x*blockDim.x + threadIdx.x;
    if (i < n4) ((float4*)dst)[i] = ((const float4*)src)[i];
}
__global__ void k_zero_int(){
    for (int i = blockIdx.x*blockDim.x + threadIdx.x; i < NN; i += gridDim.x*blockDim.x){
        g_cnt[i]=0; g_fill[i]=0;
    }
}
__global__ void k_hist(const int* __restrict__ eidx){
    int e = blockIdx.x*blockDim.x + threadIdx.x;
    if (e < EE) atomicAdd(&g_cnt[eidx[EE + e]], 1);
}
// ---- parallel 3-phase exclusive scan of g_cnt -> g_rowptr ----
__global__ void k_scan1(){
    __shared__ int sm[256];
    int t = threadIdx.x;
    int i = blockIdx.x*256 + t;
    int v = (i < NN) ? g_cnt[i] : 0;
    sm[t] = v; __syncthreads();
    #pragma unroll
    for (int off=1; off<256; off<<=1){
        int nv = (t>=off) ? sm[t-off] : 0;
        __syncthreads();
        sm[t] += nv;
        __syncthreads();
    }
    if (i < NN) g_rowptr[i] = sm[t] - v;
    if (t == 255) g_bsum[blockIdx.x] = sm[255];
}
__global__ void k_scan2(){
    __shared__ int sm[256];
    int t = threadIdx.x;
    int v = (t < SCB) ? g_bsum[t] : 0;
    sm[t] = v; __syncthreads();
    #pragma unroll
    for (int off=1; off<256; off<<=1){
        int nv = (t>=off) ? sm[t-off] : 0;
        __syncthreads();
        sm[t] += nv;
        __syncthreads();
    }
    g_boff[t] = sm[t] - v;
}
__global__ void k_scan3(){
    int t = threadIdx.x;
    int i = blockIdx.x*256 + t;
    if (i < NN) g_rowptr[i] += g_boff[blockIdx.x];
    if (i == 0) g_rowptr[NN] = EE;
}
__global__ void k_scatter(const int* __restrict__ eidx, const float* __restrict__ ew){
    int e = blockIdx.x*blockDim.x + threadIdx.x;
    if (e < EE){
        int s = eidx[e];
        int d = eidx[EE+e];
        int pos = g_rowptr[d] + atomicAdd(&g_fill[d],1);
        g_esrc[pos]=s; g_ewt[pos]=ew[e];
    }
}

// ---------------- weight precompute: Wt[ki][c][kk] (c=gate col 0..511, kk 0..255) ----------------
__global__ void k_build_wt(const float* __restrict__ convw, const float* __restrict__ wih,
                           const float* __restrict__ whh){
    int ki = blockIdx.x, c = blockIdx.y, t = threadIdx.x;
    int k = c_ki_k[ki], i = c_ki_i[ki];
    __shared__ float wr[CC];
    float aggv = 0.f;
    if (c < 384){
        wr[t] = wih[(k*384 + c)*CC + t];
        __syncthreads();
        const float* Wrow = convw + ((size_t)((k*5+i)*CC + t))*CC;
        float s = 0.f;
        #pragma unroll 8
        for (int q=0;q<CC;q++) s += Wrow[q]*wr[q];
        aggv = s;
    }
    float xv = 0.f;
    if (c < 256)       xv = whh[(k*384 + c)*CC + t];
    else if (c >= 384) xv = whh[(k*384 + 256 + (c-384))*CC + t];
    float* o = g_wt + ((size_t)ki*512 + c)*256;
    o[t]     = __uint_as_float(tf32bits(aggv));
    o[128+t] = __uint_as_float(tf32bits(xv));
}

// ---------------- CSR aggregation: agg = A @ x (warp per node, 4-wide MLP) ----------------
__global__ void k_agg(const float* __restrict__ xin, int useW){
    int node = blockIdx.x*8 + (threadIdx.x>>5);
    int lane = threadIdx.x & 31;
    int beg = g_rowptr[node], end = g_rowptr[node+1];
    float4 a0 = make_float4(0.f,0.f,0.f,0.f);
    float4 a1 = make_float4(0.f,0.f,0.f,0.f);
    int j = beg;
    int loff = lane*4;
    for (; j+4 <= end; j+=4){
        int s0 = g_esrc[j],   s1 = g_esrc[j+1];
        int s2 = g_esrc[j+2], s3 = g_esrc[j+3];
        float w0 = useW ? g_ewt[j]   : 1.f;
        float w1 = useW ? g_ewt[j+1] : 1.f;
        float w2 = useW ? g_ewt[j+2] : 1.f;
        float w3 = useW ? g_ewt[j+3] : 1.f;
        float4 v0 = *(const float4*)(xin + (size_t)s0*CC + loff);
        float4 v1 = *(const float4*)(xin + (size_t)s1*CC + loff);
        float4 v2 = *(const float4*)(xin + (size_t)s2*CC + loff);
        float4 v3 = *(const float4*)(xin + (size_t)s3*CC + loff);
        a0.x += w0*v0.x; a0.y += w0*v0.y; a0.z += w0*v0.z; a0.w += w0*v0.w;
        a1.x += w1*v1.x; a1.y += w1*v1.y; a1.z += w1*v1.z; a1.w += w1*v1.w;
        a0.x += w2*v2.x; a0.y += w2*v2.y; a0.z += w2*v2.z; a0.w += w2*v2.w;
        a1.x += w3*v3.x; a1.y += w3*v3.y; a1.z += w3*v3.z; a1.w += w3*v3.w;
    }
    for (; j < end; j++){
        int s = g_esrc[j];
        float w = useW ? g_ewt[j] : 1.f;
        float4 v = *(const float4*)(xin + (size_t)s*CC + loff);
        a0.x += w*v.x; a0.y += w*v.y; a0.z += w*v.z; a0.w += w*v.w;
    }
    float4 acc = make_float4(a0.x+a1.x, a0.y+a1.y, a0.z+a1.z, a0.w+a1.w);
    *(float4*)(g_agg + (size_t)node*CC + loff) = acc;
}

// ---------------- mma.sync tf32 fused GRU GEMM, pipelined + gate-sparse ----------------
// grid (313,4), block 256 (8 warps). CTA tile: 128 rows x (32 chans x 4 gates = 128 cols).
// K = 256: chunks 0-3 from g_agg (gates r,z,i_n active), 4-7 from xin (gates r,z,h_n).
// Warp wn = gate; inactive warp skips fragment loads + mma for its dead half.
#define KCP 36
#define BUFW (128*KCP)
__global__ void __launch_bounds__(256,2) k_gru_mma(
    const float* __restrict__ xin, float* __restrict__ xout, int ki,
    const float* __restrict__ bih, const float* __restrict__ bhh)
{
    extern __shared__ uint32_t smem[];
    uint32_t* As = smem;                 // [2][128][KCP]
    uint32_t* Ws = smem + 2*BUFW;        // [2][128][KCP]
    float*    Cs = (float*)smem;         // [128][136] (reused after GEMM)

    int tx = threadIdx.x;
    int wid = tx >> 5, l = tx & 31;
    int wm = wid & 1, wn = wid >> 1;
    int tileM = blockIdx.x * 128;
    int cb = blockIdx.y;
    const float* wt = g_wt + (size_t)ki*512*256;
    uint32_t sW = smem_u32(Ws);

    int a_r  = tx >> 3;
    int a_kq = (tx & 7) << 2;
    int b_cl = tx >> 3;
    int b_kq = (tx & 7) << 2;

    float acc[4][4][4];
    #pragma unroll
    for (int mt=0;mt<4;mt++)
        #pragma unroll
        for (int nt=0;nt<4;nt++){
            acc[mt][nt][0]=0.f; acc[mt][nt][1]=0.f; acc[mt][nt][2]=0.f; acc[mt][nt][3]=0.f;
        }

    // ---- prologue: chunk 0 (agg half: gate 3 cols dead) ----
    {
        const float* src = g_agg;
        #pragma unroll
        for (int it=0; it<4; it++){
            int r = a_r + it*32;
            float4 v = make_float4(0.f,0.f,0.f,0.f);
            int grow = tileM + r;
            if (grow < NN) v = *(const float4*)&src[(size_t)grow*CC + a_kq];
            uint4 u = make_uint4(tf32bits(v.x), tf32bits(v.y), tf32bits(v.z), tf32bits(v.w));
            *(uint4*)&As[r*KCP + a_kq] = u;
        }
        #pragma unroll
        for (int it=0; it<4; it++){
            int cl = b_cl + it*32;
            int g = cl >> 5, j = cl & 31;
            if (g != 3){
                const float* gp = &wt[(size_t)(g*128 + cb*32 + j)*256 + b_kq];
                uint32_t sa = sW + (uint32_t)(cl*KCP + b_kq)*4u;
                asm volatile("cp.async.ca.shared.global [%0], [%1], 16;" :: "r"(sa), "l"(gp));
            }
        }
        asm volatile("cp.async.commit_group;" ::: "memory");
    }

    for (int ch=0; ch<8; ch++){
        asm volatile("cp.async.wait_group 0;" ::: "memory");
        __syncthreads();

        int nbuf = (ch+1) & 1;
        float4 va[4];
        if (ch < 7){
            const float* src = (ch+1 < 4) ? g_agg : xin;
            int koff = ((ch+1)*32) & 127;
            #pragma unroll
            for (int it=0; it<4; it++){
                int r = a_r + it*32;
                float4 v = make_float4(0.f,0.f,0.f,0.f);
                int grow = tileM + r;
                if (grow < NN) v = *(const float4*)&src[(size_t)grow*CC + koff + a_kq];
                va[it] = v;
            }
            int k0 = (ch+1)*32;
            int dead = (ch+1 < 4) ? 3 : 2;
            #pragma unroll
            for (int it=0; it<4; it++){
                int cl = b_cl + it*32;
                int g = cl >> 5, j = cl & 31;
                if (g != dead){
                    const float* gp = &wt[(size_t)(g*128 + cb*32 + j)*256 + k0 + b_kq];
                    uint32_t sa = sW + (uint32_t)(nbuf*BUFW + cl*KCP + b_kq)*4u;
                    asm volatile("cp.async.ca.shared.global [%0], [%1], 16;" :: "r"(sa), "l"(gp));
                }
            }
            asm volatile("cp.async.commit_group;" ::: "memory");
        }

        // ---- mma on buffer ch&1 (skip if this warp's gate is dead this half) ----
        bool active = (ch < 4) ? (wn != 3) : (wn != 2);
        if (active){
            uint32_t* Ab = As + (ch&1)*BUFW;
            uint32_t* Wb = Ws + (ch&1)*BUFW;
            #pragma unroll
            for (int ks=0; ks<4; ks++){
                int kc = ks*8;
                uint32_t a[4][4];
                #pragma unroll
                for (int mt=0; mt<4; mt++){
                    int rb = wm*64 + mt*16 + (l>>2);
                    a[mt][0] = Ab[rb*KCP     + kc + (l&3)];
                    a[mt][1] = Ab[(rb+8)*KCP + kc + (l&3)];
                    a[mt][2] = Ab[rb*KCP     + kc + (l&3) + 4];
                    a[mt][3] = Ab[(rb+8)*KCP + kc + (l&3) + 4];
                }
                uint32_t b[4][2];
                #pragma unroll
                for (int nt=0; nt<4; nt++){
                    int nb = wn*32 + nt*8 + (l>>2);
                    b[nt][0] = Wb[nb*KCP + kc + (l&3)];
                    b[nt][1] = Wb[nb*KCP + kc + (l&3) + 4];
                }
                #pragma unroll
                for (int mt=0; mt<4; mt++)
                    #pragma unroll
                    for (int nt=0; nt<4; nt++){
                        asm volatile(
                            "mma.sync.aligned.m16n8k8.row.col.f32.tf32.tf32.f32 "
                            "{%0,%1,%2,%3}, {%4,%5,%6,%7}, {%8,%9}, {%0,%1,%2,%3};"
                            : "+f"(acc[mt][nt][0]), "+f"(acc[mt][nt][1]),
                              "+f"(acc[mt][nt][2]), "+f"(acc[mt][nt][3])
                            : "r"(a[mt][0]), "r"(a[mt][1]), "r"(a[mt][2]), "r"(a[mt][3]),
                              "r"(b[nt][0]), "r"(b[nt][1]));
                    }
            }
        }

        if (ch < 7){
            #pragma unroll
            for (int it=0; it<4; it++){
                int r = a_r + it*32;
                uint4 u = make_uint4(tf32bits(va[it].x), tf32bits(va[it].y),
                                     tf32bits(va[it].z), tf32bits(va[it].w));
                *(uint4*)&As[nbuf*BUFW + r*KCP + a_kq] = u;
            }
        }
    }

    // ---- write accumulators to Cs [128][136] ----
    __syncthreads();
    #pragma unroll
    for (int mt=0; mt<4; mt++){
        int r0 = wm*64 + mt*16 + (l>>2);
        #pragma unroll
        for (int nt=0; nt<4; nt++){
            int c0 = wn*32 + nt*8 + (l&3)*2;
            *(float2*)&Cs[r0*136 + c0]     = make_float2(acc[mt][nt][0], acc[mt][nt][1]);
            *(float2*)&Cs[(r0+8)*136 + c0] = make_float2(acc[mt][nt][2], acc[mt][nt][3]);
        }
    }
    __syncthreads();

    // ---- GRU epilogue ----
    int j = l;
    int c = cb*32 + j;
    float b_r = bih[c] + bhh[c];
    float b_z = bih[128+c] + bhh[128+c];
    float b_i = bih[256+c];
    float b_h = bhh[256+c];
    #pragma unroll
    for (int rr=0; rr<16; rr++){
        int lrow = wid*16 + rr;
        int row = tileM + lrow;
        if (row < NN){
            float sr = Cs[lrow*136 + j]      + b_r;
            float sz = Cs[lrow*136 + 32 + j] + b_z;
            float si = Cs[lrow*136 + 64 + j] + b_i;
            float sh = Cs[lrow*136 + 96 + j] + b_h;
            float r = 1.f/(1.f+expf(-sr));
            float z = 1.f/(1.f+expf(-sz));
            float n = tanhf(si + r*sh);
            float h = xin[(size_t)row*CC + c];
            xout[(size_t)row*CC + c] = (1.f-z)*n + z*h;
        }
    }
}

// ---------------- GraphNorm ----------------
__global__ void k_gn_zero(){
    int t = threadIdx.x; g_sum1[t]=0.f; g_sum2[t]=0.f;
}
__global__ void k_gn_reduce(const float* __restrict__ x, int pre){
    __shared__ float s1[256], s2[256];
    int t = threadIdx.x;
    int c = t & 127, half = t >> 7;
    float a=0.f, b=0.f;
    for (int row = blockIdx.x*2 + half; row < NN; row += gridDim.x*2){
        float v = x[(size_t)row*CC + c];
        if (pre) v = lrelu_f(v);
        a += v; b += v*v;
    }
    s1[t]=a; s2[t]=b; __syncthreads();
    if (t < 128){
        a = s1[t]+s1[t+128]; b = s2[t]+s2[t+128];
        atomicAdd(&g_sum1[c], a); atomicAdd(&g_sum2[c], b);
    }
}
__global__ void k_gn_final(const float* __restrict__ w, const float* __restrict__ bb,
                           const float* __restrict__ ms){
    int c = threadIdx.x;
    float inv = 1.f/(float)NN;
    float mean = g_sum1[c]*inv;
    float ex2  = g_sum2[c]*inv;
    float msm  = ms[c]*mean;
    float var  = ex2 - 2.f*msm*mean + msm*msm;
    float sc   = w[c]/sqrtf(var + 1e-5f);
    g_scale[c]=sc; g_shift[c]=bb[c] - sc*msm;
}
__global__ void k_gn_apply(float* __restrict__ x, int pre, int post){
    int i = blockIdx.x*blockDim.x + threadIdx.x;
    if (i >= NN*CC/4) return;
    int ci = (i & 31)*4;
    float4 v = ((float4*)x)[i];
    float vv[4] = {v.x, v.y, v.z, v.w};
    #pragma unroll
    for (int q=0;q<4;q++){
        float t = vv[q];
        if (pre) t = lrelu_f(t);
        t = g_scale[ci+q]*t + g_shift[ci+q];
        if (post) t = lrelu_f(t);
        vv[q]=t;
    }
    ((float4*)x)[i] = make_float4(vv[0],vv[1],vv[2],vv[3]);
}

// ---------------- final segment-sum ----------------
__global__ void k_out_zero(float* out){
    int i = blockIdx.x*blockDim.x + threadIdx.x;
    if (i < GG*CC) out[i]=0.f;
}
__global__ void k_final(const float* __restrict__ x, const int* __restrict__ batch,
                        float* __restrict__ out){
    int i = blockIdx.x*blockDim.x + threadIdx.x;
    if (i >= NN*CC) return;
    int row = i >> 7, c = i & 127;
    float v = lrelu_f(x[i]);
    int b = batch[row];
    atomicAdd(&out[b*CC + c], v);
}

// ---------------- host launch ----------------
extern "C" void kernel_launch(void* const* d_in, const int* in_sizes, int n_in,
                              void* d_out, int out_size){
    const float* x_in  = (const float*)d_in[0];
    const float* ew    = (const float*)d_in[1];
    const float* convw = (const float*)d_in[2];
    const float* wih   = (const float*)d_in[3];
    const float* whh   = (const float*)d_in[4];
    const float* bih   = (const float*)d_in[5];
    const float* bhh   = (const float*)d_in[6];
    const float* gnw   = (const float*)d_in[7];
    const float* gnb   = (const float*)d_in[8];
    const float* gnms  = (const float*)d_in[9];
    const int* eidx    = (const int*)d_in[10];
    const int* batch   = (const int*)d_in[11];
    float* out = (float*)d_out;

    float *xA, *xB;
    cudaGetSymbolAddress((void**)&xA, g_xA);
    cudaGetSymbolAddress((void**)&xB, g_xB);

    const int smem_gru = 4*BUFW*4;    // 73728 B (2xA + 2xB buffers; covers Cs 69632)
    static int s_attr_done = 0;
    if (!s_attr_done){
        cudaFuncSetAttribute(k_gru_mma, cudaFuncAttributeMaxDynamicSharedMemorySize, smem_gru);
        s_attr_done = 1;
    }

    k_copy<<<5000,256>>>(x_in, xA, NN*CC/4);
    k_zero_int<<<256,256>>>();
    k_hist<<<2500,256>>>(eidx);
    k_scan1<<<SCB,256>>>();
    k_scan2<<<1,256>>>();
    k_scan3<<<SCB,256>>>();
    k_scatter<<<2500,256>>>(eidx, ew);
    k_build_wt<<<dim3(NKI,512),128>>>(convw, wih, whh);

    const int steps[5]={5,4,3,2,1};
    float* cur=xA; float* nxt=xB;
    int ki=0;
    for (int k=0;k<5;k++){
        for (int i=0;i<steps[k];i++){
            k_agg<<<5000,256>>>(cur, (k<4)?1:0);
            k_gru_mma<<<dim3(313,4),256,smem_gru>>>(cur, nxt, ki, bih + k*384, bhh + k*384);
            float* tmp=cur; cur=nxt; nxt=tmp;
            ki++;
        }
        if (k<4){
            int pre  = (k==0)?0:1;
            int post = (k==0)?1:0;
            k_gn_zero<<<1,128>>>();
            k_gn_reduce<<<256,256>>>(cur, pre);
            k_gn_final<<<1,128>>>(gnw + k*CC, gnb + k*CC, gnms + k*CC);
            k_gn_apply<<<5000,256>>>(cur, pre, post);
        }
    }
    k_out_zero<<<32,256>>>(out);
    k_final<<<20000,256>>>(cur, batch, out);
}